// round 8
// baseline (speedup 1.0000x reference)
#include <cuda_runtime.h>
#include <math.h>

// ---------------------------------------------------------------------------
// ActivationPNALayer: fully-fused persistent mega-kernel.
//  0: h [N*D] f32   1: ef [E*D] f32   2: norm [N] f32
//  3: gamma1 [D]    4: beta1 [D]      5: gamma2 [D]    6: beta2 [D]
//  7: src [E] i32   8: dst [E] i32
// Output: [N*D] f32
// Phases (grid barriers between): A deg+hin | B1 tile sums | B2 scan partials
// | B3 offsets | C scatter | D agg | E bn1 stats | F bn2 stats | G output
// ---------------------------------------------------------------------------

#define N_MAX 100000
#define E_MAX 1600000
#define DD 64
#define AVG_D_LOG 2.8332133440562162f
#define EPS_STD 1e-5f
#define EPS_BN 1e-5f

#define GRID 1184                 // 148 SMs * 8 blocks, all resident
#define BLK 256
#define TILE 256                  // scan tile size
#define MAXTILES 512              // >= ceil(N_MAX/TILE) = 391

// scratch (device globals: allocation-free)
__device__ float g_hin[N_MAX * DD];
__device__ float g_ht[N_MAX * DD];
__device__ int   g_deg[N_MAX];
__device__ int   g_off[N_MAX + 1];
__device__ int   g_cur[N_MAX];
__device__ int2  g_epack[E_MAX + 1];       // +1 pad for prefetch overread
__device__ int   g_part[MAXTILES];
__device__ float g_s1[DD], g_s2[DD], g_t1[DD], g_t2[DD];
__device__ int   g_bar;

__device__ __forceinline__ void grid_barrier(int target) {
    __syncthreads();
    if (threadIdx.x == 0) {
        __threadfence();
        atomicAdd(&g_bar, 1);
        while (atomicAdd(&g_bar, 0) < target) __nanosleep(64);
    }
    __syncthreads();
}

__global__ void __launch_bounds__(BLK, 8) mega_kernel(
    const float4* __restrict__ h4, const float2* __restrict__ ef2,
    const float* __restrict__ norm,
    const float* __restrict__ gamma1, const float* __restrict__ beta1,
    const float* __restrict__ gamma2, const float* __restrict__ beta2,
    const int* __restrict__ src, const int* __restrict__ dst,
    float4* __restrict__ out4, int n, int e) {
    const int tid = threadIdx.x;
    const int bid = blockIdx.x;
    const int gsz = gridDim.x * blockDim.x;
    const int gtid = bid * blockDim.x + tid;

    __shared__ int shA[MAXTILES];
    __shared__ int shB[MAXTILES];
    __shared__ float sh1[DD], sh2[DD];

    // ======== phase A: degree count + h_in = h*norm + zero BN stats ========
    for (int i = gtid; i < e; i += gsz)
        atomicAdd(&g_deg[dst[i]], 1);
    {
        int nq = n * (DD / 4);
        float4* o4 = (float4*)g_hin;
        for (int i = gtid; i < nq; i += gsz) {
            float nv = __ldg(&norm[i >> 4]);
            float4 v = h4[i];
            v.x *= nv; v.y *= nv; v.z *= nv; v.w *= nv;
            o4[i] = v;
        }
    }
    if (bid == 0 && tid < DD) {
        g_s1[tid] = 0.f; g_s2[tid] = 0.f; g_t1[tid] = 0.f; g_t2[tid] = 0.f;
    }
    grid_barrier(GRID);

    const int ntiles = (n + TILE - 1) / TILE;

    // ======== phase B1: per-tile degree sums ========
    for (int t = bid; t < ntiles; t += gridDim.x) {
        int i = t * TILE + tid;
        shA[tid] = (i < n) ? g_deg[i] : 0;
        __syncthreads();
        for (int s = BLK / 2; s > 0; s >>= 1) {
            if (tid < s) shA[tid] += shA[tid + s];
            __syncthreads();
        }
        if (tid == 0) g_part[t] = shA[0];
        __syncthreads();
    }
    grid_barrier(2 * GRID);

    // ======== phase B2: block 0 scans the partials (exclusive) ========
    if (bid == 0) {
        for (int i = tid; i < MAXTILES; i += BLK)
            shA[i] = (i < ntiles) ? g_part[i] : 0;
        __syncthreads();
        int* a = shA;
        int* b = shB;
        for (int s = 1; s < MAXTILES; s <<= 1) {
            for (int i = tid; i < MAXTILES; i += BLK)
                b[i] = (i >= s) ? a[i] + a[i - s] : a[i];
            __syncthreads();
            int* t2 = a; a = b; b = t2;
        }
        for (int i = tid; i < ntiles; i += BLK)
            g_part[i] = (i > 0) ? a[i - 1] : 0;      // exclusive
    }
    grid_barrier(3 * GRID);

    // ======== phase B3: per-tile exclusive scan -> offsets ========
    for (int t = bid; t < ntiles; t += gridDim.x) {
        int i = t * TILE + tid;
        int v = (i < n) ? g_deg[i] : 0;
        shA[tid] = v;
        __syncthreads();
        int* a = shA;
        int* b = shB;
        for (int s = 1; s < BLK; s <<= 1) {
            b[tid] = (tid >= s) ? a[tid] + a[tid - s] : a[tid];
            __syncthreads();
            int* t2 = a; a = b; b = t2;
        }
        int excl = a[tid] - v + g_part[t];
        if (i < n) { g_off[i] = excl; g_cur[i] = excl; }
        __syncthreads();
    }
    if (bid == 0 && tid == 0) g_off[n] = e;
    grid_barrier(4 * GRID);

    // ======== phase C: CSR scatter (packed {eid, src}) ========
    for (int i = gtid; i < e; i += gsz) {
        int d = dst[i];
        int pos = atomicAdd(&g_cur[d], 1);
        g_epack[pos] = make_int2(i, src[i]);
    }
    grid_barrier(5 * GRID);

    // ======== phase D: aggregation (warp-per-node, float2 per lane) ========
    {
        const int lane = tid & 31;
        const int w = tid >> 5;
        const float2* hin2 = (const float2*)g_hin;
        float2* ht2 = (float2*)g_ht;

        for (int node = bid * 8 + w; node < n; node += gridDim.x * 8) {
            int start = g_off[node];
            int end = g_off[node + 1];
            float2 hd = hin2[node * 32 + lane];

            // u-space accumulators: u = hs + ev (shift by hd applied at the end)
            float su0 = 0.f, su1 = 0.f, qu0 = 0.f, qu1 = 0.f;
            float mx0 = -INFINITY, mx1 = -INFINITY;
            float mn0 = INFINITY, mn1 = INFINITY;

            int2 ra = __ldg(&g_epack[start]);        // prefetch first record
            #pragma unroll 4
            for (int k = start; k < end; k++) {
                int2 rb = __ldg(&g_epack[k + 1]);    // prefetch next (padded)
                float2 hs = hin2[ra.y * 32 + lane];
                float2 ev = __ldcs(&ef2[ra.x * 32 + lane]);
                float u0 = hs.x + ev.x;
                float u1 = hs.y + ev.y;
                su0 += u0; qu0 = fmaf(u0, u0, qu0);
                mx0 = fmaxf(mx0, u0); mn0 = fminf(mn0, u0);
                su1 += u1; qu1 = fmaf(u1, u1, qu1);
                mx1 = fmaxf(mx1, u1); mn1 = fminf(mn1, u1);
                ra = rb;
            }

            float fdeg = (float)(end - start);
            float inv = 1.0f / fdeg;
            float mu0 = su0 * inv, mu1 = su1 * inv;
            float var0 = fmaxf(qu0 * inv - mu0 * mu0, 0.f);   // var shift-invariant
            float var1 = fmaxf(qu1 * inv - mu1 * mu1, 0.f);
            float sd0 = sqrtf(var0 + EPS_STD);
            float sd1 = sqrtf(var1 + EPS_STD);
            float logd = logf(fdeg + 1.0f);
            float c = 1.0f + logd * (1.0f / AVG_D_LOG) + AVG_D_LOG / logd;
            // z-space mean+mx+mn+std = 3*hd + (mu+mx+mn+sd) in u-space
            float p0 = (hd.x + (3.f * hd.x + mu0 + mx0 + mn0 + sd0) * c) * (1.0f / 13.0f);
            float p1 = (hd.y + (3.f * hd.y + mu1 + mx1 + mn1 + sd1) * c) * (1.0f / 13.0f);
            ht2[node * 32 + lane] = make_float2(p0, p1);
        }
    }
    grid_barrier(6 * GRID);

    // ======== phase E: BN1 batch stats over ht ========
    const int g4 = (gtid & 15) * 4;                  // thread's 4-dim group
    const int nq4 = n * (DD / 4);
    const float4* ht4 = (const float4*)g_ht;
    {
        float s1a = 0.f, s1b = 0.f, s1c = 0.f, s1d = 0.f;
        float s2a = 0.f, s2b = 0.f, s2c = 0.f, s2d = 0.f;
        for (int idx = gtid; idx < nq4; idx += gsz) {
            float4 p = ht4[idx];
            s1a += p.x; s2a = fmaf(p.x, p.x, s2a);
            s1b += p.y; s2b = fmaf(p.y, p.y, s2b);
            s1c += p.z; s2c = fmaf(p.z, p.z, s2c);
            s1d += p.w; s2d = fmaf(p.w, p.w, s2d);
        }
        if (tid < DD) { sh1[tid] = 0.f; sh2[tid] = 0.f; }
        __syncthreads();
        atomicAdd(&sh1[g4 + 0], s1a); atomicAdd(&sh2[g4 + 0], s2a);
        atomicAdd(&sh1[g4 + 1], s1b); atomicAdd(&sh2[g4 + 1], s2b);
        atomicAdd(&sh1[g4 + 2], s1c); atomicAdd(&sh2[g4 + 2], s2c);
        atomicAdd(&sh1[g4 + 3], s1d); atomicAdd(&sh2[g4 + 3], s2d);
        __syncthreads();
        if (tid < DD) {
            atomicAdd(&g_s1[tid], sh1[tid]);
            atomicAdd(&g_s2[tid], sh2[tid]);
        }
    }
    grid_barrier(7 * GRID);

    // ---- BN1 affine ----
    float invn = 1.0f / (float)n;
    float A[4], Bc[4];
    #pragma unroll
    for (int k = 0; k < 4; k++) {
        float m = g_s1[g4 + k] * invn;
        float v = g_s2[g4 + k] * invn - m * m;
        A[k] = __ldg(&gamma1[g4 + k]) * rsqrtf(v + EPS_BN);
        Bc[k] = __ldg(&beta1[g4 + k]) - m * A[k];
    }

    // ======== phase F: y = relu((ht*A+B)*norm), BN2 stats ========
    {
        float t1a = 0.f, t1b = 0.f, t1c = 0.f, t1d = 0.f;
        float t2a = 0.f, t2b = 0.f, t2c = 0.f, t2d = 0.f;
        for (int idx = gtid; idx < nq4; idx += gsz) {
            float nv = __ldg(&norm[idx >> 4]);
            float4 p = ht4[idx];
            float y0 = fmaxf(fmaf(p.x, A[0], Bc[0]) * nv, 0.f);
            float y1 = fmaxf(fmaf(p.y, A[1], Bc[1]) * nv, 0.f);
            float y2 = fmaxf(fmaf(p.z, A[2], Bc[2]) * nv, 0.f);
            float y3 = fmaxf(fmaf(p.w, A[3], Bc[3]) * nv, 0.f);
            t1a += y0; t2a = fmaf(y0, y0, t2a);
            t1b += y1; t2b = fmaf(y1, y1, t2b);
            t1c += y2; t2c = fmaf(y2, y2, t2c);
            t1d += y3; t2d = fmaf(y3, y3, t2d);
        }
        __syncthreads();
        if (tid < DD) { sh1[tid] = 0.f; sh2[tid] = 0.f; }
        __syncthreads();
        atomicAdd(&sh1[g4 + 0], t1a); atomicAdd(&sh2[g4 + 0], t2a);
        atomicAdd(&sh1[g4 + 1], t1b); atomicAdd(&sh2[g4 + 1], t2b);
        atomicAdd(&sh1[g4 + 2], t1c); atomicAdd(&sh2[g4 + 2], t2c);
        atomicAdd(&sh1[g4 + 3], t1d); atomicAdd(&sh2[g4 + 3], t2d);
        __syncthreads();
        if (tid < DD) {
            atomicAdd(&g_t1[tid], sh1[tid]);
            atomicAdd(&g_t2[tid], sh2[tid]);
        }
    }
    grid_barrier(8 * GRID);

    // ---- BN2 affine (A/Bc kept live in registers) ----
    float C[4], Dc[4];
    #pragma unroll
    for (int k = 0; k < 4; k++) {
        float m = g_t1[g4 + k] * invn;
        float v = g_t2[g4 + k] * invn - m * m;
        C[k] = __ldg(&gamma2[g4 + k]) * rsqrtf(v + EPS_BN);
        Dc[k] = __ldg(&beta2[g4 + k]) - m * C[k];
    }

    // ======== phase G: output ========
    for (int idx = gtid; idx < nq4; idx += gsz) {
        float nv = __ldg(&norm[idx >> 4]);
        float4 p = ht4[idx];
        float y0 = fmaxf(fmaf(p.x, A[0], Bc[0]) * nv, 0.f);
        float y1 = fmaxf(fmaf(p.y, A[1], Bc[1]) * nv, 0.f);
        float y2 = fmaxf(fmaf(p.z, A[2], Bc[2]) * nv, 0.f);
        float y3 = fmaxf(fmaf(p.w, A[3], Bc[3]) * nv, 0.f);
        float4 o;
        o.x = fmaf(y0, C[0], Dc[0]);
        o.y = fmaf(y1, C[1], Dc[1]);
        o.z = fmaf(y2, C[2], Dc[2]);
        o.w = fmaf(y3, C[3], Dc[3]);
        out4[idx] = o;
    }
}

// ---------------------------------------------------------------------------
extern "C" void kernel_launch(void* const* d_in, const int* in_sizes, int n_in,
                              void* d_out, int out_size) {
    const float* h      = (const float*)d_in[0];
    const float* ef     = (const float*)d_in[1];
    const float* norm   = (const float*)d_in[2];
    const float* gamma1 = (const float*)d_in[3];
    const float* beta1  = (const float*)d_in[4];
    const float* gamma2 = (const float*)d_in[5];
    const float* beta2  = (const float*)d_in[6];
    const int*   src    = (const int*)d_in[7];
    const int*   dst    = (const int*)d_in[8];

    int n = in_sizes[2];
    int e = in_sizes[7];
    if (n > N_MAX) n = N_MAX;
    if (e > E_MAX) e = E_MAX;

    void *p_deg = nullptr, *p_bar = nullptr;
    cudaGetSymbolAddress(&p_deg, g_deg);
    cudaGetSymbolAddress(&p_bar, g_bar);
    cudaMemsetAsync(p_deg, 0, (size_t)n * sizeof(int));
    cudaMemsetAsync(p_bar, 0, sizeof(int));

    mega_kernel<<<GRID, BLK>>>((const float4*)h, (const float2*)ef, norm,
                               gamma1, beta1, gamma2, beta2, src, dst,
                               (float4*)d_out, n, e);
}

// round 9
// speedup vs baseline: 1.0717x; 1.0717x over previous
#include <cuda_runtime.h>
#include <math.h>

// ---------------------------------------------------------------------------
// ActivationPNALayer: fused PNA aggregation + tower + 2x BatchNorm
//  0: h [N*D] f32   1: ef [E*D] f32   2: norm [N] f32
//  3: gamma1 [D]    4: beta1 [D]      5: gamma2 [D]    6: beta2 [D]
//  7: src [E] i32   8: dst [E] i32
// Output: [N*D] f32
// ---------------------------------------------------------------------------

#define N_MAX 100000
#define E_MAX 1600000
#define DD 64
#define AVG_D_LOG 2.8332133440562162f
#define EPS_STD 1e-5f
#define EPS_BN 1e-5f

#define SCAN_T 512
#define SCAN_BMAX 256

// scratch (device globals: allocation-free)
__device__ float g_hin[N_MAX * DD];
__device__ float g_ht[N_MAX * DD];
__device__ int   g_deg[N_MAX];
__device__ int   g_off[N_MAX + 1];
__device__ int   g_cur[N_MAX];
__device__ int2  g_epack[E_MAX + 1];              // +1 pad for prefetch overread
__device__ unsigned long long g_scan_state[SCAN_BMAX];
__device__ float g_s1[DD], g_s2[DD], g_t1[DD], g_t2[DD];
__device__ int   g_bar;                           // grid barrier counter

// ------------------------------------------------- degree count
__global__ void __launch_bounds__(256) deg_kernel(
    const int* __restrict__ dst, int e) {
    int total = gridDim.x * blockDim.x;
    for (int i = blockIdx.x * blockDim.x + threadIdx.x; i < e; i += total)
        atomicAdd(&g_deg[dst[i]], 1);
}

// ------------------------------------------------- single-pass scan (lookback)
__global__ void __launch_bounds__(SCAN_T) scan_kernel(int n, int e_total) {
    __shared__ int sh[SCAN_T];
    __shared__ int sh_prefix;
    int bid = blockIdx.x, tid = threadIdx.x;
    int i = bid * SCAN_T + tid;
    int v = (i < n) ? g_deg[i] : 0;
    sh[tid] = v;
    __syncthreads();
    for (int s = 1; s < SCAN_T; s <<= 1) {
        int t = (tid >= s) ? sh[tid - s] : 0;
        __syncthreads();
        sh[tid] += t;
        __syncthreads();
    }
    int total = sh[SCAN_T - 1];

    if (tid == 0) {
        if (bid == 0) {
            sh_prefix = 0;
            atomicExch(&g_scan_state[0], (2ULL << 32) | (unsigned)total);
        } else {
            atomicExch(&g_scan_state[bid], (1ULL << 32) | (unsigned)total);
            unsigned long long prefix = 0;
            int j = bid - 1;
            while (true) {
                unsigned long long s = atomicAdd(&g_scan_state[j], 0ULL);
                unsigned f = (unsigned)(s >> 32);
                if (f == 2u) { prefix += (unsigned)s; break; }
                if (f == 1u) { prefix += (unsigned)s; j--; }
            }
            atomicExch(&g_scan_state[bid],
                       (2ULL << 32) | (unsigned)(prefix + (unsigned)total));
            sh_prefix = (int)prefix;
        }
    }
    if (bid == 0) {   // zero BN-stat accumulators for downstream kernels
        if (tid < DD) g_s1[tid] = 0.f;
        else if (tid < 2 * DD) g_s2[tid - DD] = 0.f;
        else if (tid < 3 * DD) g_t1[tid - 2 * DD] = 0.f;
        else if (tid < 4 * DD) g_t2[tid - 3 * DD] = 0.f;
    }
    __syncthreads();
    int excl = sh_prefix + sh[tid] - v;
    if (i < n) { g_off[i] = excl; g_cur[i] = excl; }
    if (i == 0) g_off[n] = e_total;
}

// ------------------------------------------------- CSR scatter + h_in = h*norm
// hin stream (pure bandwidth) overlaps the atomic-latency-bound scatter.
__global__ void __launch_bounds__(256) scatter_hin_kernel(
    const int* __restrict__ dst, const int* __restrict__ src,
    const float4* __restrict__ h4, const float* __restrict__ norm,
    int n, int e) {
    int total = gridDim.x * blockDim.x;
    int tid = blockIdx.x * blockDim.x + threadIdx.x;
    for (int i = tid; i < e; i += total) {
        int d = dst[i];
        int pos = atomicAdd(&g_cur[d], 1);
        g_epack[pos] = make_int2(i, src[i]);
    }
    int nq = n * (DD / 4);
    float4* o4 = (float4*)g_hin;
    for (int i = tid; i < nq; i += total) {
        float nv = __ldg(&norm[i >> 4]);
        float4 v = h4[i];
        v.x *= nv; v.y *= nv; v.z *= nv; v.w *= nv;
        o4[i] = v;
    }
}

// ------------------------------------------------- aggregation
// warp-per-node, lane owns dims (2*lane, 2*lane+1) as float2.
// u-space accumulation (u = hs+ev; hd shift applied in epilogue) and
// one-ahead record prefetch (epack padded +1).
__global__ void __launch_bounds__(256, 8) agg_kernel(
    const float2* __restrict__ ef2, int n) {
    const int lane = threadIdx.x & 31;
    const int w = threadIdx.x >> 5;               // warp in block = node slot

    int node0 = blockIdx.x * 8 + w;
    int nodeStride = gridDim.x * 8;

    const float2* hin2 = (const float2*)g_hin;
    float2* ht2 = (float2*)g_ht;

    for (int node = node0; node < n; node += nodeStride) {
        int start = g_off[node];
        int end = g_off[node + 1];
        float2 hd = hin2[node * 32 + lane];

        float su0 = 0.f, su1 = 0.f, qu0 = 0.f, qu1 = 0.f;
        float mx0 = -INFINITY, mx1 = -INFINITY;
        float mn0 = INFINITY, mn1 = INFINITY;

        int2 ra = __ldg(&g_epack[start]);          // prefetch first record
        #pragma unroll 4
        for (int k = start; k < end; k++) {
            int2 rb = __ldg(&g_epack[k + 1]);      // prefetch next (padded)
            float2 hs = hin2[ra.y * 32 + lane];
            float2 ev = __ldcs(&ef2[ra.x * 32 + lane]);
            float u0 = hs.x + ev.x;
            float u1 = hs.y + ev.y;
            su0 += u0; qu0 = fmaf(u0, u0, qu0);
            mx0 = fmaxf(mx0, u0); mn0 = fminf(mn0, u0);
            su1 += u1; qu1 = fmaf(u1, u1, qu1);
            mx1 = fmaxf(mx1, u1); mn1 = fminf(mn1, u1);
            ra = rb;
        }

        float fdeg = (float)(end - start);
        float inv = 1.0f / fdeg;
        float mu0 = su0 * inv, mu1 = su1 * inv;
        float var0 = fmaxf(qu0 * inv - mu0 * mu0, 0.f);   // var shift-invariant
        float var1 = fmaxf(qu1 * inv - mu1 * mu1, 0.f);
        float sd0 = sqrtf(var0 + EPS_STD);
        float sd1 = sqrtf(var1 + EPS_STD);
        float logd = logf(fdeg + 1.0f);
        float c = 1.0f + logd * (1.0f / AVG_D_LOG) + AVG_D_LOG / logd;
        // z-space mean+mx+mn+std = 4*hd + (mu+mx+mn+sd)_u; plus hd from cat
        float p0 = (hd.x + (3.f * hd.x + mu0 + mx0 + mn0 + sd0) * c) * (1.0f / 13.0f);
        float p1 = (hd.y + (3.f * hd.y + mu1 + mx1 + mn1 + sd1) * c) * (1.0f / 13.0f);
        ht2[node * 32 + lane] = make_float2(p0, p1);
    }
}

// ------------------------------------------------- fused BN1-stats / BN2 / out
// Persistent grid (148*8 blocks, launch_bounds(256,8) => all resident) with
// software grid barriers. ht stays L2-resident across the three passes.
__device__ __forceinline__ void grid_barrier(int target) {
    __syncthreads();
    if (threadIdx.x == 0) {
        __threadfence();
        atomicAdd(&g_bar, 1);
        while (atomicAdd(&g_bar, 0) < target) __nanosleep(64);
    }
    __syncthreads();
}

__global__ void __launch_bounds__(256, 8) bn_fused_kernel(
    const float* __restrict__ norm, const float* __restrict__ gamma1,
    const float* __restrict__ beta1, const float* __restrict__ gamma2,
    const float* __restrict__ beta2, float4* __restrict__ out4, int n) {
    const int tid = threadIdx.x;
    const int stride = gridDim.x * blockDim.x;       // multiple of 16
    const int idx0 = blockIdx.x * blockDim.x + tid;
    const int g = (idx0 & 15) * 4;                   // this thread's dim group
    const int nq4 = n * (DD / 4);
    const float4* ht4 = (const float4*)g_ht;

    __shared__ float sh1[DD], sh2[DD];

    // ---- pass 1: BN1 batch stats from ht ----
    float s1a = 0.f, s1b = 0.f, s1c = 0.f, s1d = 0.f;
    float s2a = 0.f, s2b = 0.f, s2c = 0.f, s2d = 0.f;
    for (int idx = idx0; idx < nq4; idx += stride) {
        float4 p = ht4[idx];
        s1a += p.x; s2a = fmaf(p.x, p.x, s2a);
        s1b += p.y; s2b = fmaf(p.y, p.y, s2b);
        s1c += p.z; s2c = fmaf(p.z, p.z, s2c);
        s1d += p.w; s2d = fmaf(p.w, p.w, s2d);
    }
    if (tid < DD) { sh1[tid] = 0.f; sh2[tid] = 0.f; }
    __syncthreads();
    atomicAdd(&sh1[g + 0], s1a); atomicAdd(&sh2[g + 0], s2a);
    atomicAdd(&sh1[g + 1], s1b); atomicAdd(&sh2[g + 1], s2b);
    atomicAdd(&sh1[g + 2], s1c); atomicAdd(&sh2[g + 2], s2c);
    atomicAdd(&sh1[g + 3], s1d); atomicAdd(&sh2[g + 3], s2d);
    __syncthreads();
    if (tid < DD) {
        atomicAdd(&g_s1[tid], sh1[tid]);
        atomicAdd(&g_s2[tid], sh2[tid]);
    }
    grid_barrier(gridDim.x);

    // ---- BN1 affine for this thread's 4 dims ----
    float invn = 1.0f / (float)n;
    float A[4], Bc[4];
    #pragma unroll
    for (int k = 0; k < 4; k++) {
        float m = g_s1[g + k] * invn;
        float v = g_s2[g + k] * invn - m * m;
        A[k] = __ldg(&gamma1[g + k]) * rsqrtf(v + EPS_BN);
        Bc[k] = __ldg(&beta1[g + k]) - m * A[k];
    }

    // ---- pass 2: y = relu((ht*A+B)*norm), BN2 stats ----
    float t1a = 0.f, t1b = 0.f, t1c = 0.f, t1d = 0.f;
    float t2a = 0.f, t2b = 0.f, t2c = 0.f, t2d = 0.f;
    for (int idx = idx0; idx < nq4; idx += stride) {
        float nv = __ldg(&norm[idx >> 4]);
        float4 p = ht4[idx];
        float y0 = fmaxf(fmaf(p.x, A[0], Bc[0]) * nv, 0.f);
        float y1 = fmaxf(fmaf(p.y, A[1], Bc[1]) * nv, 0.f);
        float y2 = fmaxf(fmaf(p.z, A[2], Bc[2]) * nv, 0.f);
        float y3 = fmaxf(fmaf(p.w, A[3], Bc[3]) * nv, 0.f);
        t1a += y0; t2a = fmaf(y0, y0, t2a);
        t1b += y1; t2b = fmaf(y1, y1, t2b);
        t1c += y2; t2c = fmaf(y2, y2, t2c);
        t1d += y3; t2d = fmaf(y3, y3, t2d);
    }
    __syncthreads();
    if (tid < DD) { sh1[tid] = 0.f; sh2[tid] = 0.f; }
    __syncthreads();
    atomicAdd(&sh1[g + 0], t1a); atomicAdd(&sh2[g + 0], t2a);
    atomicAdd(&sh1[g + 1], t1b); atomicAdd(&sh2[g + 1], t2b);
    atomicAdd(&sh1[g + 2], t1c); atomicAdd(&sh2[g + 2], t2c);
    atomicAdd(&sh1[g + 3], t1d); atomicAdd(&sh2[g + 3], t2d);
    __syncthreads();
    if (tid < DD) {
        atomicAdd(&g_t1[tid], sh1[tid]);
        atomicAdd(&g_t2[tid], sh2[tid]);
    }
    grid_barrier(2 * gridDim.x);

    // ---- BN2 affine ----
    float C[4], Dc[4];
    #pragma unroll
    for (int k = 0; k < 4; k++) {
        float m = g_t1[g + k] * invn;
        float v = g_t2[g + k] * invn - m * m;
        C[k] = __ldg(&gamma2[g + k]) * rsqrtf(v + EPS_BN);
        Dc[k] = __ldg(&beta2[g + k]) - m * C[k];
    }

    // ---- pass 3: output ----
    for (int idx = idx0; idx < nq4; idx += stride) {
        float nv = __ldg(&norm[idx >> 4]);
        float4 p = ht4[idx];
        float y0 = fmaxf(fmaf(p.x, A[0], Bc[0]) * nv, 0.f);
        float y1 = fmaxf(fmaf(p.y, A[1], Bc[1]) * nv, 0.f);
        float y2 = fmaxf(fmaf(p.z, A[2], Bc[2]) * nv, 0.f);
        float y3 = fmaxf(fmaf(p.w, A[3], Bc[3]) * nv, 0.f);
        float4 o;
        o.x = fmaf(y0, C[0], Dc[0]);
        o.y = fmaf(y1, C[1], Dc[1]);
        o.z = fmaf(y2, C[2], Dc[2]);
        o.w = fmaf(y3, C[3], Dc[3]);
        out4[idx] = o;
    }
}

// ---------------------------------------------------------------------------
extern "C" void kernel_launch(void* const* d_in, const int* in_sizes, int n_in,
                              void* d_out, int out_size) {
    const float* h      = (const float*)d_in[0];
    const float* ef     = (const float*)d_in[1];
    const float* norm   = (const float*)d_in[2];
    const float* gamma1 = (const float*)d_in[3];
    const float* beta1  = (const float*)d_in[4];
    const float* gamma2 = (const float*)d_in[5];
    const float* beta2  = (const float*)d_in[6];
    const int*   src    = (const int*)d_in[7];
    const int*   dst    = (const int*)d_in[8];

    int n = in_sizes[2];
    int e = in_sizes[7];
    if (n > N_MAX) n = N_MAX;
    if (e > E_MAX) e = E_MAX;

    const int B = 256;
    const int GRID_PERSIST = 148 * 8;              // one full resident wave
    int scan_blocks = (n + SCAN_T - 1) / SCAN_T;

    void *p_deg = nullptr, *p_state = nullptr, *p_bar = nullptr;
    cudaGetSymbolAddress(&p_deg, g_deg);
    cudaGetSymbolAddress(&p_state, g_scan_state);
    cudaGetSymbolAddress(&p_bar, g_bar);
    cudaMemsetAsync(p_deg, 0, (size_t)n * sizeof(int));
    cudaMemsetAsync(p_state, 0, (size_t)SCAN_BMAX * sizeof(unsigned long long));
    cudaMemsetAsync(p_bar, 0, sizeof(int));

    deg_kernel<<<2048, B>>>(dst, e);
    scan_kernel<<<scan_blocks, SCAN_T>>>(n, e);
    scatter_hin_kernel<<<GRID_PERSIST, B>>>(dst, src, (const float4*)h, norm, n, e);
    agg_kernel<<<GRID_PERSIST, B>>>((const float2*)ef, n);
    bn_fused_kernel<<<GRID_PERSIST, B>>>(norm, gamma1, beta1, gamma2, beta2,
                                         (float4*)d_out, n);
}